// round 10
// baseline (speedup 1.0000x reference)
#include <cuda_runtime.h>

#define BB 8
#define CC 128
#define KK 19
#define NPIX 65536
#define BN (BB*NPIX)
#define NPBLK 512            // k_pred blocks = 64*8
#define NSEG (NPIX/32)       // 32-px sort segments per batch

// ---------------- scratch (device globals; no allocation) ----------------
__device__ float2 g_em[BN];              // sorted per 32-px seg: (e, idx_in_256chunk)
__device__ ulonglong2 g_cnt32[BB*NSEG];  // packed 19x6-bit class counts per segment
__device__ float  g_Zp[NPBLK*KK];        // per-block partial sum of exp
__device__ float  g_Cp[NPBLK*KK];        // per-block partial pixel count
__device__ float  g_Xs[BB*KK*CC];        // unweighted segment sums of x
__device__ float  g_Xw[BB*KK*CC];        // exp-weighted segment sums of x
__device__ float  g_gmat[BB*KK*CC];      // g[b][k][d]
__device__ float  g_S1[BB*CC*KK];        // S1[b][d][k]

// ---- pass 1 (fused): argmax + e=exp(p) + counting-sort per 32-px segment ----
#define FPB 1024
__global__ void __launch_bounds__(256) k_pred(const float* __restrict__ preds){
    const int b  = blockIdx.y;
    const int bx = blockIdx.x;
    const int p0 = bx*FPB;
    const int t  = threadIdx.x;
    const int bid  = b*64 + bx;

    // zero accumulator slices: 2*BB*KK*CC = 38912 = 512*76
    if (t < 76){
        int z = bid*76 + t;
        if (z < BB*KK*CC) g_Xs[z] = 0.f;
        else              g_Xw[z - BB*KK*CC] = 0.f;
    }

    const float4* r0 = (const float4*)(preds + (size_t)b*KK*NPIX + p0);
    float4 v = __ldg(&r0[t]);
    float bv[4] = {v.x, v.y, v.z, v.w};
    int   bk[4] = {0,0,0,0};
    #pragma unroll
    for (int k=1;k<KK;k++){
        float4 u = __ldg(&r0[t + k*(NPIX/4)]);
        if (u.x > bv[0]){ bv[0]=u.x; bk[0]=k; }
        if (u.y > bv[1]){ bv[1]=u.y; bk[1]=k; }
        if (u.z > bv[2]){ bv[2]=u.z; bk[2]=k; }
        if (u.w > bv[3]){ bv[3]=u.w; bk[3]=k; }
    }
    float ev[4];
    #pragma unroll
    for (int j=0;j<4;j++) ev[j] = expf(bv[j]);   // shift-invariant softmax

    __shared__ int    segCnt[32][20];
    __shared__ int    segStart[32][20];
    __shared__ float  sZ[KK];
    __shared__ float2 sEMst[FPB];                // staged sorted output (8 KB)
    for (int i=t;i<32*20;i+=256) segCnt[i/20][i%20] = 0;
    if (t < KK) sZ[t] = 0.f;
    __syncthreads();

    int rk[4];
    #pragma unroll
    for (int j=0;j<4;j++){
        int i = 4*t + j;
        rk[j] = atomicAdd(&segCnt[i>>5][bk[j]], 1);
        atomicAdd(&sZ[bk[j]], ev[j]);
    }
    __syncthreads();
    if (t < 32){
        int s = 0;
        ulonglong2 cc; cc.x = 0ull; cc.y = 0ull;
        #pragma unroll
        for (int k=0;k<KK;k++){
            segStart[t][k] = s;
            int c = segCnt[t][k];
            s += c;
            if (k < 10) cc.x |= (unsigned long long)c << (6*k);
            else        cc.y |= (unsigned long long)c << (6*(k-10));
        }
        g_cnt32[(size_t)b*NSEG + bx*32 + t] = cc;
    }
    __syncthreads();

    #pragma unroll
    for (int j=0;j<4;j++){
        int i = 4*t + j;
        int seg = i >> 5;
        int pos = segStart[seg][bk[j]] + rk[j];
        sEMst[seg*32 + pos] = make_float2(ev[j], __int_as_float(i & 255));
    }
    __syncthreads();
    // coalesced global write: 1024 float2 = 512 float4 ops, 2 per thread
    {
        const float4* src = (const float4*)sEMst;
        float4* dst = (float4*)(g_em + (size_t)b*NPIX + p0);
        dst[t]       = src[t];
        dst[t + 256] = src[t + 256];
    }
    if (t < KK){
        g_Zp[bid*KK+t] = sZ[t];
        int c = 0;
        #pragma unroll
        for (int w=0;w<32;w++) c += segCnt[w][t];
        g_Cp[bid*KK+t] = (float)c;
    }
}

// ---------------- pass 2: heavy segment sums over x ----------------
// 256-px chunks, each warp count-walks its 32-px sorted segment: no per-pixel
// class test, unrolled 19-class loop with packed 6-bit trip counts.
#define PTILE 1024
#define PCH   256
#define NCHUNK (PTILE/PCH)                // 4
#define XSTRIDE 258                       // 1032 B/row: 2-way LDS conflict max
#define XWORDS (32*XSTRIDE)               // 8256 floats per buffer
#define OFF_EM   (2*XWORDS*4)             // 66048
#define OFF_CNT  (OFF_EM + 2*PCH*8)       // 70144
#define SMEM_BYTES (OFF_CNT + 2*8*16)     // 70400 (dynamic)

__device__ __forceinline__ void cpasync8(unsigned saddr, const void* gaddr){
    asm volatile("cp.async.ca.shared.global [%0], [%1], 8;" :: "r"(saddr), "l"(gaddr));
}
__device__ __forceinline__ void cpcommit(){ asm volatile("cp.async.commit_group;"); }
template<int N> __device__ __forceinline__ void cpwait(){ asm volatile("cp.async.wait_group %0;" :: "n"(N)); }

extern __shared__ unsigned char s_dyn[];

__global__ void __launch_bounds__(256, 3) k_segsum(const float* __restrict__ x){
    float*      sXf  = (float*)s_dyn;
    float2*     sEM  = (float2*)(s_dyn + OFF_EM);
    ulonglong2* sCnt = (ulonglong2*)(s_dyn + OFF_CNT);

    const int b    = blockIdx.z;
    const int c0   = blockIdx.y*32;
    const int pix0 = blockIdx.x*PTILE;
    const int t    = threadIdx.x;
    const int warp = t >> 5;
    const int lane = t & 31;

    const float* xb = x + (size_t)b*CC*NPIX + (size_t)c0*NPIX + pix0;
    unsigned sbase = (unsigned)__cvta_generic_to_shared(s_dyn);

    auto prefetch = [&](int ch, int buf){
        const float* gsrc = xb + ch*PCH;
        unsigned sx = sbase + (unsigned)buf*(XWORDS*4);
        // 32 rows x 128 8B-units = 4096 ops / 256 threads = 16 per thread
        #pragma unroll
        for (int j=0;j<16;j++){
            int u    = t + j*256;
            int row  = u >> 7;
            int unit = u & 127;
            cpasync8(sx + (unsigned)(row*XSTRIDE + unit*2)*4,
                     gsrc + (size_t)row*NPIX + unit*2);
        }
        // em: 256 float2 = 256 x 8B, one per thread
        cpasync8(sbase + OFF_EM + (unsigned)buf*(PCH*8) + (unsigned)t*8,
                 g_em + (size_t)b*NPIX + pix0 + ch*PCH + t);
        // counts: 8 segs x 16B = 16 x 8B
        if (t < 16){
            const char* csrc = (const char*)(g_cnt32 + (size_t)b*NSEG + (pix0>>5) + ch*8);
            cpasync8(sbase + OFF_CNT + (unsigned)buf*128 + (unsigned)t*8, csrc + t*8);
        }
        cpcommit();
    };

    float accS[KK], accW[KK];
    #pragma unroll
    for (int k=0;k<KK;k++){ accS[k]=0.f; accW[k]=0.f; }

    prefetch(0, 0);
    for (int ch=0; ch<NCHUNK; ++ch){
        int buf = ch & 1;
        if (ch+1 < NCHUNK) prefetch(ch+1, buf^1);
        if (ch+1 < NCHUNK) cpwait<1>(); else cpwait<0>();
        __syncthreads();

        const float*  xrow = &sXf[buf*XWORDS + lane*XSTRIDE];
        const float2* ep   = &sEM[buf*PCH + warp*32];
        ulonglong2 cc = sCnt[buf*8 + warp];       // uniform

        int pos = 0;
        #pragma unroll
        for (int k=0;k<KK;k++){
            int cnt = (k < 10) ? (int)((cc.x >> (6*k)) & 63ull)
                               : (int)((cc.y >> (6*(k-10))) & 63ull);
            if (cnt > 0){
                float ls = 0.f, lw = 0.f;
                do {
                    float2 em = ep[pos++];        // uniform LDS.64
                    float v = xrow[__float_as_int(em.y)];
                    ls += v;
                    lw = fmaf(v, em.x, lw);
                } while (--cnt);
                accS[k] += ls; accW[k] += lw;     // compile-time index
            }
        }
        __syncthreads();
    }

    // ---- cross-warp smem tree reduce (x tile dead; reuse), then global RED ----
    float* red = (float*)s_dyn;   // [KK][8][32] = 19456 B
    #pragma unroll
    for (int k=0;k<KK;k++) red[(k*8+warp)*32+lane] = accS[k];
    __syncthreads();
    for (int it=t; it<KK*32; it+=256){
        int k = it >> 5, ln = it & 31;
        float s = 0.f;
        #pragma unroll
        for (int w=0;w<8;w++) s += red[(k*8+w)*32+ln];
        atomicAdd(&g_Xs[(b*KK+k)*CC + c0 + ln], s);
    }
    __syncthreads();
    #pragma unroll
    for (int k=0;k<KK;k++) red[(k*8+warp)*32+lane] = accW[k];
    __syncthreads();
    for (int it=t; it<KK*32; it+=256){
        int k = it >> 5, ln = it & 31;
        float s = 0.f;
        #pragma unroll
        for (int w=0;w<8;w++) s += red[(k*8+w)*32+ln];
        atomicAdd(&g_Xw[(b*KK+k)*CC + c0 + ln], s);
    }
}

// ---------------- pass 3: tiny GEMMs, one block per (k,b), streamed weights ----
__global__ void __launch_bounds__(128) k_smallmm(
        const float* __restrict__ w1, const float* __restrict__ b1,
        const float* __restrict__ w2, const float* __restrict__ b2){
    const int k = blockIdx.x, b = blockIdx.y, t = threadIdx.x;  // t = d
    __shared__ float sXs[CC], sXw[CC];
    __shared__ float sZred[64], sCred[64];
    __shared__ float sZv, sCv;
    sXs[t] = g_Xs[(b*KK+k)*CC + t];
    sXw[t] = g_Xw[(b*KK+k)*CC + t];
    if (t < 64){
        sZred[t] = g_Zp[(b*64+t)*KK + k];
        sCred[t] = g_Cp[(b*64+t)*KK + k];
    }
    __syncthreads();
    if (t == 0){
        float z=0.f, c=0.f;
        #pragma unroll
        for (int i=0;i<64;i++){ z += sZred[i]; c += sCred[i]; }
        sZv = fmaxf(z, 1e-30f); sCv = c;
    }
    __syncthreads();

    const float4* w1r = (const float4*)(w1 + t*CC);
    const float4* w2r = (const float4*)(w2 + t*CC);
    float sa = 0.f, ga = 0.f;
    #pragma unroll 8
    for (int j=0;j<32;j++){
        float4 a = __ldg(&w1r[j]);
        float4 q = __ldg(&w2r[j]);
        sa = fmaf(a.x, sXs[4*j+0], sa); sa = fmaf(a.y, sXs[4*j+1], sa);
        sa = fmaf(a.z, sXs[4*j+2], sa); sa = fmaf(a.w, sXs[4*j+3], sa);
        ga = fmaf(q.x, sXw[4*j+0], ga); ga = fmaf(q.y, sXw[4*j+1], ga);
        ga = fmaf(q.z, sXw[4*j+2], ga); ga = fmaf(q.w, sXw[4*j+3], ga);
    }
    g_gmat[(b*KK+k)*CC + t] = ga/sZv + b2[t];
    g_S1[(b*CC+t)*KK + k]   = sa + b1[t]*sCv;
}

// ---------------- pass 4: gc = S1 @ g / sqrt(C), row softmax ----------------
__global__ void __launch_bounds__(128) k_out(float* __restrict__ out){
    int b = blockIdx.y, d1 = blockIdx.x, t = threadIdx.x;
    __shared__ float s1[KK];
    __shared__ float redm[4], reds[4];
    if (t < KK) s1[t] = g_S1[(b*CC+d1)*KK + t];
    __syncthreads();
    float acc = 0.f;
    const float* gb = g_gmat + b*KK*CC + t;
    #pragma unroll
    for (int k=0;k<KK;k++) acc = fmaf(s1[k], gb[k*CC], acc);
    acc *= 0.08838834764831845f;
    float m = acc;
    #pragma unroll
    for (int o=16;o;o>>=1) m = fmaxf(m, __shfl_xor_sync(0xffffffffu, m, o));
    if ((t&31)==0) redm[t>>5] = m;
    __syncthreads();
    m = fmaxf(fmaxf(redm[0],redm[1]), fmaxf(redm[2],redm[3]));
    float e = expf(acc - m);
    float s = e;
    #pragma unroll
    for (int o=16;o;o>>=1) s += __shfl_xor_sync(0xffffffffu, s, o);
    if ((t&31)==0) reds[t>>5] = s;
    __syncthreads();
    s = reds[0]+reds[1]+reds[2]+reds[3];
    out[((size_t)(b*CC+d1))*CC + t] = e/s;
}

// ---------------- launch ----------------
extern "C" void kernel_launch(void* const* d_in, const int* in_sizes, int n_in,
                              void* d_out, int out_size){
    const float* x     = (const float*)d_in[0];
    const float* preds = (const float*)d_in[1];
    const float* w1    = (const float*)d_in[2];
    const float* b1    = (const float*)d_in[3];
    const float* w2    = (const float*)d_in[4];
    const float* b2    = (const float*)d_in[5];
    float* out = (float*)d_out;

    static int smem_set = 0;
    if (!smem_set){
        cudaFuncSetAttribute(k_segsum, cudaFuncAttributeMaxDynamicSharedMemorySize, SMEM_BYTES);
        smem_set = 1;
    }

    k_pred   <<<dim3(NPIX/FPB, BB), 256>>>(preds);
    k_segsum <<<dim3(NPIX/PTILE, CC/32, BB), 256, SMEM_BYTES>>>(x);
    k_smallmm<<<dim3(KK, BB), 128>>>(w1, b1, w2, b2);
    k_out    <<<dim3(CC, BB), CC>>>(out);
    (void)in_sizes; (void)n_in; (void)out_size;
}

// round 11
// speedup vs baseline: 1.6253x; 1.6253x over previous
#include <cuda_runtime.h>

#define BB 8
#define CC 128
#define KK 19
#define NPIX 65536
#define BN (BB*NPIX)
#define NPBLK 512            // k_pred blocks = 64*8

// ---------------- scratch (device globals; no allocation) ----------------
__device__ float2 g_em[BN];            // sorted per 128-seg: (e, bits(idx<<8|widx<<5|cls))
__device__ float  g_Zp[NPBLK*KK];      // per-block partial sum of exp
__device__ float  g_Cp[NPBLK*KK];      // per-block partial pixel count
__device__ float  g_Xs[BB*KK*CC];      // unweighted segment sums of x
__device__ float  g_Xw[BB*KK*CC];      // exp-weighted segment sums of x
__device__ float  g_gmat[BB*KK*CC];    // g[b][k][d]
__device__ float  g_S1[BB*CC*KK];      // S1[b][d][k]

// ---- pass 1 (fused): argmax + e=exp(p) + counting-sort per 128-seg ----
#define FPB 1024
__global__ void __launch_bounds__(256) k_pred(const float* __restrict__ preds){
    const int b  = blockIdx.y;
    const int bx = blockIdx.x;
    const int p0 = bx*FPB;
    const int t  = threadIdx.x;
    const int warp = t >> 5;
    const int lane = t & 31;
    const int bid  = b*64 + bx;

    // zero accumulator slices: 2*BB*KK*CC = 38912 = 512*76
    if (t < 76){
        int z = bid*76 + t;
        if (z < BB*KK*CC) g_Xs[z] = 0.f;
        else              g_Xw[z - BB*KK*CC] = 0.f;
    }

    const float4* r0 = (const float4*)(preds + (size_t)b*KK*NPIX + p0);
    float4 v = __ldg(&r0[t]);
    float bv[4] = {v.x, v.y, v.z, v.w};
    int   bk[4] = {0,0,0,0};
    #pragma unroll
    for (int k=1;k<KK;k++){
        float4 u = __ldg(&r0[t + k*(NPIX/4)]);
        if (u.x > bv[0]){ bv[0]=u.x; bk[0]=k; }
        if (u.y > bv[1]){ bv[1]=u.y; bk[1]=k; }
        if (u.z > bv[2]){ bv[2]=u.z; bk[2]=k; }
        if (u.w > bv[3]){ bv[3]=u.w; bk[3]=k; }
    }
    float ev[4];
    #pragma unroll
    for (int j=0;j<4;j++) ev[j] = expf(bv[j]);   // shift-invariant softmax

    __shared__ int   segCnt[8][20];
    __shared__ int   segStart[8][20];
    __shared__ float sZ[KK];
    if (t < 8*20) segCnt[t/20][t%20] = 0;
    if (t < KK)   sZ[t] = 0.f;
    __syncthreads();

    int rk[4];
    #pragma unroll
    for (int j=0;j<4;j++){
        unsigned mm = __match_any_sync(0xffffffffu, bk[j]);
        int ldr = __ffs(mm) - 1;
        int base = 0;
        if (lane == ldr) base = atomicAdd(&segCnt[warp][bk[j]], __popc(mm));
        base = __shfl_sync(0xffffffffu, base, ldr);
        rk[j] = base + __popc(mm & ((1u<<lane)-1u));
        atomicAdd(&sZ[bk[j]], ev[j]);
    }
    __syncthreads();
    if (t < 8){
        int s = 0;
        #pragma unroll
        for (int k=0;k<KK;k++){ segStart[t][k] = s; s += segCnt[t][k]; }
    }
    __syncthreads();

    const int segbase = b*NPIX + p0 + warp*128;
    const int i0 = 4*lane;
    #pragma unroll
    for (int j=0;j<4;j++){
        int pos = segStart[warp][bk[j]] + rk[j];
        int tag = ((pos >> 4) << 5) | bk[j];          // window id | class
        g_em[segbase + pos] = make_float2(ev[j], __int_as_float(((i0+j)<<8) | tag));
    }
    if (t < KK){
        g_Zp[bid*KK+t] = sZ[t];
        int c = 0;
        #pragma unroll
        for (int w=0;w<8;w++) c += segCnt[w][t];
        g_Cp[bid*KK+t] = (float)c;
    }
}

// ---------------- pass 2: heavy segment sums over x ----------------
#define PTILE 2048
#define PCH   128
#define NCHUNK (PTILE/PCH)                // 16
#define XSTRIDE 130                       // 520 B/row: 2-way LDS conflict max
#define XWORDS (32*XSTRIDE)
#define EMSTRIDE (PCH+1)                  // +1 sentinel slot
#define OFF_EM   (2*XWORDS*4)             // 33280 (16B aligned)
#define SMEM_BYTES (OFF_EM + 2*EMSTRIDE*8)  // 35344

__device__ __forceinline__ void cpasync8(unsigned saddr, const void* gaddr){
    asm volatile("cp.async.ca.shared.global [%0], [%1], 8;" :: "r"(saddr), "l"(gaddr));
}
__device__ __forceinline__ void cpcommit(){ asm volatile("cp.async.commit_group;"); }
template<int N> __device__ __forceinline__ void cpwait(){ asm volatile("cp.async.wait_group %0;" :: "n"(N)); }

__global__ void __launch_bounds__(256, 4) k_segsum(const float* __restrict__ x){
    __shared__ __align__(16) unsigned char smemRaw[SMEM_BYTES];
    float*  sXf = (float*)smemRaw;
    float2* sEM = (float2*)(smemRaw + OFF_EM);

    const int b    = blockIdx.z;
    const int c0   = blockIdx.y*32;
    const int pix0 = blockIdx.x*PTILE;
    const int t    = threadIdx.x;
    const int warp = t >> 5;
    const int lane = t & 31;

    const float* xb = x + (size_t)b*CC*NPIX + (size_t)c0*NPIX + pix0;
    unsigned sbase = (unsigned)__cvta_generic_to_shared(smemRaw);

    // sentinel tag 255 at slot PCH of each buffer (real tags <= 242)
    if (t < 2) sEM[t*EMSTRIDE + PCH] = make_float2(0.f, __int_as_float(255));

    auto prefetch = [&](int ch, int buf){
        const float* gsrc = xb + ch*PCH;
        unsigned sx = sbase + (unsigned)buf*(XWORDS*4);
        #pragma unroll
        for (int j=0;j<8;j++){
            int u    = t + j*256;
            int row  = u >> 6;
            int unit = u & 63;
            cpasync8(sx + (unsigned)(row*XSTRIDE + unit*2)*4,
                     gsrc + (size_t)row*NPIX + unit*2);
        }
        if (t < 128){
            cpasync8(sbase + OFF_EM + (unsigned)buf*(EMSTRIDE*8) + (unsigned)t*8,
                     g_em + (size_t)b*NPIX + pix0 + ch*PCH + t);
        }
        cpcommit();
    };

    float accS[KK], accW[KK];
    #pragma unroll
    for (int k=0;k<KK;k++){ accS[k]=0.f; accW[k]=0.f; }

    prefetch(0, 0);
    for (int ch=0; ch<NCHUNK; ++ch){
        int buf = ch & 1;
        if (ch+1 < NCHUNK) prefetch(ch+1, buf^1);
        if (ch+1 < NCHUNK) cpwait<1>(); else cpwait<0>();
        __syncthreads();

        const float*  xrow = &sXf[buf*XWORDS + lane*XSTRIDE];
        const float2* ep   = &sEM[buf*EMSTRIDE];

        const int wend = warp*16 + 16;
        int p = warp*16;
        float2 em = ep[p];
        while (p < wend){                         // once per RUN
            int tag = __float_as_int(em.y) & 255;
            int k   = tag & 31;
            float ls = 0.f, lw = 0.f;
            do {                                  // per pixel: 1 tag compare only
                float v = xrow[__float_as_int(em.y) >> 8];
                ls += v;
                lw = fmaf(v, em.x, lw);
                ++p;
                em = ep[p];                       // safe: sentinel at slot 128
            } while ((__float_as_int(em.y) & 255) == tag);
            switch(k){                            // once per run
            case 0:  accS[0] +=ls; accW[0] +=lw; break;
            case 1:  accS[1] +=ls; accW[1] +=lw; break;
            case 2:  accS[2] +=ls; accW[2] +=lw; break;
            case 3:  accS[3] +=ls; accW[3] +=lw; break;
            case 4:  accS[4] +=ls; accW[4] +=lw; break;
            case 5:  accS[5] +=ls; accW[5] +=lw; break;
            case 6:  accS[6] +=ls; accW[6] +=lw; break;
            case 7:  accS[7] +=ls; accW[7] +=lw; break;
            case 8:  accS[8] +=ls; accW[8] +=lw; break;
            case 9:  accS[9] +=ls; accW[9] +=lw; break;
            case 10: accS[10]+=ls; accW[10]+=lw; break;
            case 11: accS[11]+=ls; accW[11]+=lw; break;
            case 12: accS[12]+=ls; accW[12]+=lw; break;
            case 13: accS[13]+=ls; accW[13]+=lw; break;
            case 14: accS[14]+=ls; accW[14]+=lw; break;
            case 15: accS[15]+=ls; accW[15]+=lw; break;
            case 16: accS[16]+=ls; accW[16]+=lw; break;
            case 17: accS[17]+=ls; accW[17]+=lw; break;
            default: accS[18]+=ls; accW[18]+=lw; break;
            }
        }
        __syncthreads();
    }

    // ---- cross-warp smem tree reduce (x tile dead; reuse), then global RED ----
    float* red = (float*)smemRaw;   // [KK][8][32] = 19456 B < OFF_EM
    #pragma unroll
    for (int k=0;k<KK;k++) red[(k*8+warp)*32+lane] = accS[k];
    __syncthreads();
    for (int it=t; it<KK*32; it+=256){
        int k = it >> 5, ln = it & 31;
        float s = 0.f;
        #pragma unroll
        for (int w=0;w<8;w++) s += red[(k*8+w)*32+ln];
        atomicAdd(&g_Xs[(b*KK+k)*CC + c0 + ln], s);
    }
    __syncthreads();
    #pragma unroll
    for (int k=0;k<KK;k++) red[(k*8+warp)*32+lane] = accW[k];
    __syncthreads();
    for (int it=t; it<KK*32; it+=256){
        int k = it >> 5, ln = it & 31;
        float s = 0.f;
        #pragma unroll
        for (int w=0;w<8;w++) s += red[(k*8+w)*32+ln];
        atomicAdd(&g_Xw[(b*KK+k)*CC + c0 + ln], s);
    }
}

// ---------------- pass 3: tiny GEMMs, one block per (k,b), streamed weights ----
__global__ void __launch_bounds__(128) k_smallmm(
        const float* __restrict__ w1, const float* __restrict__ b1,
        const float* __restrict__ w2, const float* __restrict__ b2){
    const int k = blockIdx.x, b = blockIdx.y, t = threadIdx.x;  // t = d
    __shared__ float sXs[CC], sXw[CC];
    __shared__ float sZred[64], sCred[64];
    __shared__ float sZv, sCv;
    sXs[t] = g_Xs[(b*KK+k)*CC + t];
    sXw[t] = g_Xw[(b*KK+k)*CC + t];
    if (t < 64){
        sZred[t] = g_Zp[(b*64+t)*KK + k];
        sCred[t] = g_Cp[(b*64+t)*KK + k];
    }
    __syncthreads();
    if (t == 0){
        float z=0.f, c=0.f;
        #pragma unroll
        for (int i=0;i<64;i++){ z += sZred[i]; c += sCred[i]; }
        sZv = fmaxf(z, 1e-30f); sCv = c;
    }
    __syncthreads();

    const float4* w1r = (const float4*)(w1 + t*CC);
    const float4* w2r = (const float4*)(w2 + t*CC);
    float sa = 0.f, ga = 0.f;
    #pragma unroll 8
    for (int j=0;j<32;j++){
        float4 a = __ldg(&w1r[j]);
        float4 q = __ldg(&w2r[j]);
        sa = fmaf(a.x, sXs[4*j+0], sa); sa = fmaf(a.y, sXs[4*j+1], sa);
        sa = fmaf(a.z, sXs[4*j+2], sa); sa = fmaf(a.w, sXs[4*j+3], sa);
        ga = fmaf(q.x, sXw[4*j+0], ga); ga = fmaf(q.y, sXw[4*j+1], ga);
        ga = fmaf(q.z, sXw[4*j+2], ga); ga = fmaf(q.w, sXw[4*j+3], ga);
    }
    g_gmat[(b*KK+k)*CC + t] = ga/sZv + b2[t];
    g_S1[(b*CC+t)*KK + k]   = sa + b1[t]*sCv;
}

// ---------------- pass 4: gc = S1 @ g / sqrt(C), row softmax ----------------
__global__ void __launch_bounds__(128) k_out(float* __restrict__ out){
    int b = blockIdx.y, d1 = blockIdx.x, t = threadIdx.x;
    __shared__ float s1[KK];
    __shared__ float redm[4], reds[4];
    if (t < KK) s1[t] = g_S1[(b*CC+d1)*KK + t];
    __syncthreads();
    float acc = 0.f;
    const float* gb = g_gmat + b*KK*CC + t;
    #pragma unroll
    for (int k=0;k<KK;k++) acc = fmaf(s1[k], gb[k*CC], acc);
    acc *= 0.08838834764831845f;
    float m = acc;
    #pragma unroll
    for (int o=16;o;o>>=1) m = fmaxf(m, __shfl_xor_sync(0xffffffffu, m, o));
    if ((t&31)==0) redm[t>>5] = m;
    __syncthreads();
    m = fmaxf(fmaxf(redm[0],redm[1]), fmaxf(redm[2],redm[3]));
    float e = expf(acc - m);
    float s = e;
    #pragma unroll
    for (int o=16;o;o>>=1) s += __shfl_xor_sync(0xffffffffu, s, o);
    if ((t&31)==0) reds[t>>5] = s;
    __syncthreads();
    s = reds[0]+reds[1]+reds[2]+reds[3];
    out[((size_t)(b*CC+d1))*CC + t] = e/s;
}

// ---------------- launch ----------------
extern "C" void kernel_launch(void* const* d_in, const int* in_sizes, int n_in,
                              void* d_out, int out_size){
    const float* x     = (const float*)d_in[0];
    const float* preds = (const float*)d_in[1];
    const float* w1    = (const float*)d_in[2];
    const float* b1    = (const float*)d_in[3];
    const float* w2    = (const float*)d_in[4];
    const float* b2    = (const float*)d_in[5];
    float* out = (float*)d_out;

    k_pred   <<<dim3(NPIX/FPB, BB), 256>>>(preds);
    k_segsum <<<dim3(NPIX/PTILE, CC/32, BB), 256>>>(x);
    k_smallmm<<<dim3(KK, BB), 128>>>(w1, b1, w2, b2);
    k_out    <<<dim3(CC, BB), CC>>>(out);
    (void)in_sizes; (void)n_in; (void)out_size;
}